// round 2
// baseline (speedup 1.0000x reference)
#include <cuda_runtime.h>
#include <cuda_bf16.h>
#include <cstdint>

#define B_DIM 4096
#define D_DIM 1024
#define K_DIM 3000
#define KF4   750          // K_DIM / 4
#define KP    3008         // padded column count
#define IEPS  20.0f        // 1/epsilon
#define ITMP  10.0f        // 1/temperature
#define TEMP  0.1f
#define EPIT  132          // epilogue smem pitch (floats): 132*4=528 ≡ 0 mod 16

// ---------------- scratch (static __device__ allocations) ----------------
__device__ __align__(256) float          g_scores[2][(size_t)B_DIM * K_DIM];   // 98.3 MB
__device__ __align__(256) __nv_bfloat16  g_zb[2][(size_t)B_DIM * D_DIM];       // 16.8 MB
__device__ __align__(256) __nv_bfloat16  g_Wb[(size_t)K_DIM * D_DIM];          //  6.1 MB
__device__ __align__(256) float          g_c [2][3][KP];     // column sums per sinkhorn iter
__device__ __align__(256) float          g_vv[2][3][KP];     // v = 1/(K*c)
__device__ __align__(256) float          g_p [2][3][B_DIM];  // row sums
__device__ __align__(256) float          g_uu[2][3][B_DIM];  // u = 1/(B*p)
__device__ __align__(256) float          g_E [2][B_DIM];     // softmax denominators
__device__ __align__(256) float          g_A [2];            // cross terms

// ---------------- small helpers ----------------
__device__ __forceinline__ float warp_red(float v) {
    #pragma unroll
    for (int o = 16; o; o >>= 1) v += __shfl_xor_sync(0xffffffffu, v, o);
    return v;
}

__global__ void zero_kernel() {
    int idx = blockIdx.x * blockDim.x + threadIdx.x;
    if (idx < 2 * 3 * KP)   ((float*)g_c)[idx] = 0.0f;
    if (idx < 2 * B_DIM)    ((float*)g_E)[idx] = 0.0f;
    if (idx < 2)            g_A[idx] = 0.0f;
}

__global__ void cvt_kernel(const float* __restrict__ z1,
                           const float* __restrict__ z2,
                           const float* __restrict__ W) {
    const int n1 = B_DIM * D_DIM;        // 4,194,304
    const int nw = K_DIM * D_DIM;        // 3,072,000
    int stride = gridDim.x * blockDim.x;
    for (int i = blockIdx.x * blockDim.x + threadIdx.x; i < n1; i += stride) {
        g_zb[0][i] = __float2bfloat16(z1[i]);
        g_zb[1][i] = __float2bfloat16(z2[i]);
        if (i < nw) g_Wb[i] = __float2bfloat16(W[i]);
    }
}

// ---------------- GEMM: mma.sync bf16, 128x128x32 tiles, 3-stage cp.async ----------------
#define STAGE_ELEMS 5120   // 128 * 40 halves per operand per stage
#define LDT 40             // smem row pitch (halves): 80B rows, 16B-aligned
#define DYN_SMEM 69632     // max(pipeline 61440, epilogue 128*132*4=67584)

__device__ __forceinline__ void cp16(void* sdst, const void* gsrc) {
    uint32_t s = (uint32_t)__cvta_generic_to_shared(sdst);
    asm volatile("cp.async.cg.shared.global [%0], [%1], 16;" :: "r"(s), "l"(gsrc));
}

#define LDSM4(R0,R1,R2,R3,ADDR) \
    asm volatile("ldmatrix.sync.aligned.m8n8.x4.shared.b16 {%0,%1,%2,%3}, [%4];" \
                 : "=r"(R0), "=r"(R1), "=r"(R2), "=r"(R3) : "r"(ADDR))

__device__ __forceinline__ void mma16816(float* c, const uint32_t* a, const uint32_t* b) {
    asm volatile(
        "mma.sync.aligned.m16n8k16.row.col.f32.bf16.bf16.f32 "
        "{%0,%1,%2,%3}, {%4,%5,%6,%7}, {%8,%9}, {%0,%1,%2,%3};"
        : "+f"(c[0]), "+f"(c[1]), "+f"(c[2]), "+f"(c[3])
        : "r"(a[0]), "r"(a[1]), "r"(a[2]), "r"(a[3]), "r"(b[0]), "r"(b[1]));
}

__device__ __forceinline__ void load_stage(__nv_bfloat16* As, __nv_bfloat16* Bs,
                                           const __nv_bfloat16* Ag, int n_base,
                                           int s, int kt, int tid) {
    #pragma unroll
    for (int h = 0; h < 2; h++) {
        int c = tid + h * 256;
        int r = c >> 2, c16 = c & 3;
        cp16(As + s * STAGE_ELEMS + r * LDT + c16 * 8,
             Ag + (size_t)r * D_DIM + kt * 32 + c16 * 8);
    }
    #pragma unroll
    for (int h = 0; h < 2; h++) {
        int c = tid + h * 256;
        int r = c >> 2, c16 = c & 3;
        int gn = n_base + r; if (gn >= K_DIM) gn = K_DIM - 1;   // clamp tail (results discarded)
        cp16(Bs + s * STAGE_ELEMS + r * LDT + c16 * 8,
             g_Wb + (size_t)gn * D_DIM + kt * 32 + c16 * 8);
    }
    asm volatile("cp.async.commit_group;");
}

__global__ void __launch_bounds__(256) gemm_kernel() {
    extern __shared__ char smem_raw[];
    __nv_bfloat16* As = reinterpret_cast<__nv_bfloat16*>(smem_raw);
    __nv_bfloat16* Bs = As + 3 * STAGE_ELEMS;
    float* epi = reinterpret_cast<float*>(smem_raw);   // reused after mainloop, [128][EPIT]

    const int tid = threadIdx.x;
    const int bn = blockIdx.x, bm = blockIdx.y, mat = blockIdx.z;
    const __nv_bfloat16* Ag = g_zb[mat] + (size_t)bm * 128 * D_DIM;
    const int n_base = bn * 128;

    load_stage(As, Bs, Ag, n_base, 0, 0, tid);
    load_stage(As, Bs, Ag, n_base, 1, 1, tid);

    float acc[2][8][4];
    #pragma unroll
    for (int a = 0; a < 2; a++)
        #pragma unroll
        for (int b = 0; b < 8; b++)
            #pragma unroll
            for (int c = 0; c < 4; c++) acc[a][b][c] = 0.0f;

    const int lane = tid & 31, wid = tid >> 5;
    const int wm = wid & 3, wn = wid >> 2;     // 4 (M) x 2 (N) warps; warp tile 32x64

    for (int kt = 0; kt < 32; kt++) {
        asm volatile("cp.async.wait_group 1;");
        __syncthreads();
        if (kt + 2 < 32) load_stage(As, Bs, Ag, n_base, (kt + 2) % 3, kt + 2, tid);
        const int cur = kt % 3;
        uint32_t a_base = (uint32_t)__cvta_generic_to_shared(As + cur * STAGE_ELEMS);
        uint32_t b_base = (uint32_t)__cvta_generic_to_shared(Bs + cur * STAGE_ELEMS);
        #pragma unroll
        for (int ks = 0; ks < 2; ks++) {
            uint32_t af[2][4];
            #pragma unroll
            for (int mt = 0; mt < 2; mt++) {
                int row = wm * 32 + mt * 16 + (lane & 15);
                int col = ks * 16 + (lane >> 4) * 8;
                uint32_t ad = a_base + (uint32_t)(row * LDT + col) * 2;
                LDSM4(af[mt][0], af[mt][1], af[mt][2], af[mt][3], ad);
            }
            uint32_t bfr[8][2];
            #pragma unroll
            for (int np = 0; np < 4; np++) {
                int mi = lane >> 3;
                int nr = wn * 64 + np * 16 + (mi >> 1) * 8 + (lane & 7);
                int kc = ks * 16 + (mi & 1) * 8;
                uint32_t ad = b_base + (uint32_t)(nr * LDT + kc) * 2;
                uint32_t r0, r1, r2, r3;
                LDSM4(r0, r1, r2, r3, ad);
                bfr[np * 2][0] = r0; bfr[np * 2][1] = r1;
                bfr[np * 2 + 1][0] = r2; bfr[np * 2 + 1][1] = r3;
            }
            #pragma unroll
            for (int mt = 0; mt < 2; mt++)
                #pragma unroll
                for (int nt = 0; nt < 8; nt++)
                    mma16816(acc[mt][nt], af[mt], bfr[nt]);
        }
    }
    asm volatile("cp.async.wait_group 0;");
    __syncthreads();

    // ---- epilogue: stage fp32 scores into smem [128][EPIT] ----
    #pragma unroll
    for (int mt = 0; mt < 2; mt++) {
        #pragma unroll
        for (int nt = 0; nt < 8; nt++) {
            int r = wm * 32 + mt * 16 + (lane >> 2);
            int cb = wn * 64 + nt * 8 + 2 * (lane & 3);
            epi[r * EPIT + cb]           = acc[mt][nt][0];
            epi[r * EPIT + cb + 1]       = acc[mt][nt][1];
            epi[(r + 8) * EPIT + cb]     = acc[mt][nt][2];
            epi[(r + 8) * EPIT + cb + 1] = acc[mt][nt][3];
        }
    }
    __syncthreads();

    int nvalid = K_DIM - n_base; if (nvalid > 128) nvalid = 128;   // 128 or 56 (both %4==0)

    // coalesced score stores: warp w copies rows [16w, 16w+16)
    for (int r = wid * 16; r < wid * 16 + 16; r++) {
        int gi = bm * 128 + r;
        int c = lane * 4;
        if (c < nvalid) {
            float4 val = *reinterpret_cast<float4*>(&epi[r * EPIT + c]);
            *reinterpret_cast<float4*>(g_scores[mat] + (size_t)gi * K_DIM + n_base + c) = val;
        }
    }

    // fused reductions: col-sums of exp(s/eps) (sinkhorn iter-1) and row-sums of exp(s/T)
    if (tid < 128) {
        int c = tid;
        if (c < nvalid) {
            float s = 0.0f;
            #pragma unroll 4
            for (int r = 0; r < 128; r++) s += __expf(epi[r * EPIT + c] * IEPS);
            atomicAdd(&g_c[mat][0][n_base + c], s);
        }
    } else {
        int r = tid - 128;
        float s = 0.0f;
        for (int c = 0; c < nvalid; c++) s += __expf(epi[r * EPIT + c] * ITMP);
        atomicAdd(&g_E[mat][bm * 128 + r], s);
    }
}

// ---------------- sinkhorn vector transforms ----------------
__global__ void vcalc(int iter) {
    int idx = blockIdx.x * blockDim.x + threadIdx.x;
    if (idx < 2 * K_DIM) {
        int m = idx / K_DIM, j = idx % K_DIM;
        g_vv[m][iter][j] = 1.0f / ((float)K_DIM * g_c[m][iter][j]);
    }
}

__global__ void ucalc(int iter) {
    int idx = blockIdx.x * blockDim.x + threadIdx.x;
    if (idx < 2 * B_DIM) {
        int m = idx / B_DIM, i = idx % B_DIM;
        g_uu[m][iter][i] = 1.0f / ((float)B_DIM * g_p[m][iter][i]);
    }
}

// ---------------- row pass: p[i] = sum_j exp(s_ij/eps) * v[j] ----------------
__global__ void __launch_bounds__(256) row_pass(int iter) {
    const int mat = blockIdx.y;
    const int r0 = blockIdx.x * 32;
    const int wid = threadIdx.x >> 5, lane = threadIdx.x & 31;
    const float4* v4 = reinterpret_cast<const float4*>(g_vv[mat][iter]);
    for (int rr = wid; rr < 32; rr += 8) {
        int i = r0 + rr;
        const float4* srow = reinterpret_cast<const float4*>(g_scores[mat] + (size_t)i * K_DIM);
        float acc = 0.0f;
        for (int j = lane; j < KF4; j += 32) {
            float4 s = srow[j]; float4 v = v4[j];
            acc += __expf(s.x * IEPS) * v.x + __expf(s.y * IEPS) * v.y
                 + __expf(s.z * IEPS) * v.z + __expf(s.w * IEPS) * v.w;
        }
        acc = warp_red(acc);
        if (lane == 0) g_p[mat][iter][i] = acc;
    }
}

// ---------------- col pass: c_out[j] = sum_i exp(s_ij/eps) * u[i] ----------------
__global__ void __launch_bounds__(256) col_pass(int iter) {
    const int mat = blockIdx.z;
    const int j4 = blockIdx.x * 256 + threadIdx.x;   // float4 column index
    const int r0 = blockIdx.y * 128;
    if (j4 >= KF4) return;
    const float* uu = g_uu[mat][iter];
    const float4* base = reinterpret_cast<const float4*>(g_scores[mat]);
    float ax = 0.f, ay = 0.f, az = 0.f, aw = 0.f;
    for (int r = 0; r < 128; r++) {
        int i = r0 + r;
        float u = uu[i];
        float4 s = base[(size_t)i * KF4 + j4];
        ax += __expf(s.x * IEPS) * u;
        ay += __expf(s.y * IEPS) * u;
        az += __expf(s.z * IEPS) * u;
        aw += __expf(s.w * IEPS) * u;
    }
    float* c = g_c[mat][iter + 1];
    atomicAdd(&c[j4 * 4 + 0], ax);
    atomicAdd(&c[j4 * 4 + 1], ay);
    atomicAdd(&c[j4 * 4 + 2], az);
    atomicAdd(&c[j4 * 4 + 3], aw);
}

// ---------------- final cross terms: A1 = sum q2*s1, A2 = sum q1*s2 ----------------
__global__ void __launch_bounds__(256) cross_kernel() {
    const int NF4 = B_DIM * KF4;
    const float* u1 = g_uu[0][2];
    const float* u2 = g_uu[1][2];
    const float4* v1 = reinterpret_cast<const float4*>(g_vv[0][2]);
    const float4* v2 = reinterpret_cast<const float4*>(g_vv[1][2]);
    const float4* s1 = reinterpret_cast<const float4*>(g_scores[0]);
    const float4* s2 = reinterpret_cast<const float4*>(g_scores[1]);
    float a1 = 0.f, a2 = 0.f;
    int stride = gridDim.x * blockDim.x;
    for (int idx = blockIdx.x * blockDim.x + threadIdx.x; idx < NF4; idx += stride) {
        int i = idx / KF4;
        int jj = idx - i * KF4;
        float4 x1 = s1[idx], x2 = s2[idx];
        float4 w1 = v1[jj], w2 = v2[jj];
        float uu1 = u1[i], uu2 = u2[i];
        a1 += uu2 * (__expf(x2.x * IEPS) * w2.x * x1.x + __expf(x2.y * IEPS) * w2.y * x1.y
                   + __expf(x2.z * IEPS) * w2.z * x1.z + __expf(x2.w * IEPS) * w2.w * x1.w);
        a2 += uu1 * (__expf(x1.x * IEPS) * w1.x * x2.x + __expf(x1.y * IEPS) * w1.y * x2.y
                   + __expf(x1.z * IEPS) * w1.z * x2.z + __expf(x1.w * IEPS) * w1.w * x2.w);
    }
    a1 = warp_red(a1); a2 = warp_red(a2);
    __shared__ float sa1[8], sa2[8];
    int lane = threadIdx.x & 31, wid = threadIdx.x >> 5;
    if (lane == 0) { sa1[wid] = a1; sa2[wid] = a2; }
    __syncthreads();
    if (threadIdx.x == 0) {
        float t1 = 0.f, t2 = 0.f;
        for (int w = 0; w < 8; w++) { t1 += sa1[w]; t2 += sa2[w]; }
        atomicAdd(&g_A[0], t1);
        atomicAdd(&g_A[1], t2);
    }
}

// ---------------- finalize: loss = -(1/2)[(A1+A2)/(B*T) - (sum log E)/B^2] ----------------
__global__ void finalize_kernel(float* out) {
    float l = 0.0f;
    for (int i = threadIdx.x; i < B_DIM; i += blockDim.x)
        l += __logf(g_E[0][i]) + __logf(g_E[1][i]);
    l = warp_red(l);
    __shared__ float sl[8];
    int lane = threadIdx.x & 31, wid = threadIdx.x >> 5;
    if (lane == 0) sl[wid] = l;
    __syncthreads();
    if (threadIdx.x == 0) {
        float tot = 0.f;
        for (int w = 0; w < 8; w++) tot += sl[w];
        float A = g_A[0] + g_A[1];
        float loss = -0.5f * (A / ((float)B_DIM * TEMP) - tot / ((float)B_DIM * (float)B_DIM));
        out[0] = loss;
    }
}

// ---------------- launch ----------------
extern "C" void kernel_launch(void* const* d_in, const int* in_sizes, int n_in,
                              void* d_out, int out_size) {
    const float* z1 = (const float*)d_in[0];
    const float* z2 = (const float*)d_in[1];
    const float* W  = (const float*)d_in[2];
    float* out = (float*)d_out;

    cudaFuncSetAttribute(gemm_kernel, cudaFuncAttributeMaxDynamicSharedMemorySize, DYN_SMEM);

    zero_kernel<<<(2 * 3 * KP + 255) / 256, 256>>>();
    cvt_kernel<<<2048, 256>>>(z1, z2, W);

    dim3 ggrid(24, 32, 2);   // 24 N-tiles, 32 M-tiles, 2 matrices
    gemm_kernel<<<ggrid, 256, DYN_SMEM>>>();

    // sinkhorn: iter-1 col-sums came from the GEMM epilogue
    for (int it = 0; it < 3; it++) {
        vcalc<<<(2 * K_DIM + 255) / 256, 256>>>(it);
        row_pass<<<dim3(128, 2), 256>>>(it);
        ucalc<<<(2 * B_DIM + 255) / 256, 256>>>(it);
        if (it < 2) col_pass<<<dim3(3, 32, 2), 256>>>(it);   // writes g_c[.][it+1]
    }

    cross_kernel<<<1184, 256>>>();
    finalize_kernel<<<1, 256>>>(out);
}

// round 4
// speedup vs baseline: 1.1200x; 1.1200x over previous
#include <cuda_runtime.h>
#include <cuda_bf16.h>
#include <cstdint>

#define B_DIM 4096
#define D_DIM 1024
#define K_DIM 3000
#define KC8   375          // K_DIM / 8 : 16B chunks per bf16 row
#define KP    3008
#define IEPS  20.0f        // 1/epsilon
#define ITMP  10.0f        // 1/temperature
#define TEMP  0.1f
#define EPIT  132          // epilogue smem pitch (floats), 16B-aligned rows

// ---------------- scratch ----------------
__device__ __align__(256) __nv_bfloat16  g_scores[2][(size_t)B_DIM * K_DIM];  // 49.2 MB
__device__ __align__(256) __nv_bfloat16  g_zb[2][(size_t)B_DIM * D_DIM];      // 16.8 MB
__device__ __align__(256) __nv_bfloat16  g_Wb[(size_t)K_DIM * D_DIM];         //  6.1 MB
__device__ __align__(256) float          g_c [2][3][KP];     // col sums per iter
__device__ __align__(256) float          g_p [2][3][B_DIM];  // row sums per iter
__device__ __align__(256) float          g_E [2][B_DIM];     // exp(s/T) row sums
__device__ __align__(256) float          g_t [2][B_DIM];     // cross-term row vectors

// ---------------- helpers ----------------
__device__ __forceinline__ float warp_red(float v) {
    #pragma unroll
    for (int o = 16; o; o >>= 1) v += __shfl_xor_sync(0xffffffffu, v, o);
    return v;
}
__device__ __forceinline__ float frcp(float x) {
    float r; asm("rcp.approx.f32 %0, %1;" : "=f"(r) : "f"(x)); return r;
}
__device__ __forceinline__ void unpack8(uint4 ch, float* f) {
    __nv_bfloat162* h = reinterpret_cast<__nv_bfloat162*>(&ch);
    #pragma unroll
    for (int k = 0; k < 4; k++) {
        float2 t = __bfloat1622float2(h[k]);
        f[2 * k] = t.x; f[2 * k + 1] = t.y;
    }
}

// ---------------- cvt + zero (fused) ----------------
__global__ void cvt_kernel(const float* __restrict__ z1,
                           const float* __restrict__ z2,
                           const float* __restrict__ W) {
    const int n1 = B_DIM * D_DIM;
    const int nw = K_DIM * D_DIM;
    int idx0 = blockIdx.x * blockDim.x + threadIdx.x;
    if (idx0 < 2 * 3 * KP)  ((float*)g_c)[idx0] = 0.0f;
    if (idx0 < 2 * B_DIM)   ((float*)g_E)[idx0] = 0.0f;
    int stride = gridDim.x * blockDim.x;
    for (int i = idx0; i < n1; i += stride) {
        g_zb[0][i] = __float2bfloat16(z1[i]);
        g_zb[1][i] = __float2bfloat16(z2[i]);
        if (i < nw) g_Wb[i] = __float2bfloat16(W[i]);
    }
}

// ---------------- GEMM: mma.sync bf16, 128x128x32, 3-stage cp.async ----------------
#define STAGE_ELEMS 5120
#define LDT 40
#define DYN_SMEM 69632

__device__ __forceinline__ void cp16(void* sdst, const void* gsrc) {
    uint32_t s = (uint32_t)__cvta_generic_to_shared(sdst);
    asm volatile("cp.async.cg.shared.global [%0], [%1], 16;" :: "r"(s), "l"(gsrc));
}

#define LDSM4(R0,R1,R2,R3,ADDR) \
    asm volatile("ldmatrix.sync.aligned.m8n8.x4.shared.b16 {%0,%1,%2,%3}, [%4];" \
                 : "=r"(R0), "=r"(R1), "=r"(R2), "=r"(R3) : "r"(ADDR))

__device__ __forceinline__ void mma16816(float* c, const uint32_t* a, const uint32_t* b) {
    asm volatile(
        "mma.sync.aligned.m16n8k16.row.col.f32.bf16.bf16.f32 "
        "{%0,%1,%2,%3}, {%4,%5,%6,%7}, {%8,%9}, {%0,%1,%2,%3};"
        : "+f"(c[0]), "+f"(c[1]), "+f"(c[2]), "+f"(c[3])
        : "r"(a[0]), "r"(a[1]), "r"(a[2]), "r"(a[3]), "r"(b[0]), "r"(b[1]));
}

__device__ __forceinline__ void load_stage(__nv_bfloat16* As, __nv_bfloat16* Bs,
                                           const __nv_bfloat16* Ag, int n_base,
                                           int s, int kt, int tid) {
    #pragma unroll
    for (int h = 0; h < 2; h++) {
        int c = tid + h * 256;
        int r = c >> 2, c16 = c & 3;
        cp16(As + s * STAGE_ELEMS + r * LDT + c16 * 8,
             Ag + (size_t)r * D_DIM + kt * 32 + c16 * 8);
    }
    #pragma unroll
    for (int h = 0; h < 2; h++) {
        int c = tid + h * 256;
        int r = c >> 2, c16 = c & 3;
        int gn = n_base + r; if (gn >= K_DIM) gn = K_DIM - 1;   // clamp tail
        cp16(Bs + s * STAGE_ELEMS + r * LDT + c16 * 8,
             g_Wb + (size_t)gn * D_DIM + kt * 32 + c16 * 8);
    }
    asm volatile("cp.async.commit_group;");
}

__global__ void __launch_bounds__(256, 2) gemm_kernel() {
    extern __shared__ char smem_raw[];
    __nv_bfloat16* As = reinterpret_cast<__nv_bfloat16*>(smem_raw);
    __nv_bfloat16* Bs = As + 3 * STAGE_ELEMS;
    float* epi = reinterpret_cast<float*>(smem_raw);   // reused post-mainloop

    const int tid = threadIdx.x;
    const int bn = blockIdx.x, bm = blockIdx.y, mat = blockIdx.z;
    const __nv_bfloat16* Ag = g_zb[mat] + (size_t)bm * 128 * D_DIM;
    const int n_base = bn * 128;

    load_stage(As, Bs, Ag, n_base, 0, 0, tid);
    load_stage(As, Bs, Ag, n_base, 1, 1, tid);

    float acc[2][8][4];
    #pragma unroll
    for (int a = 0; a < 2; a++)
        #pragma unroll
        for (int b = 0; b < 8; b++)
            #pragma unroll
            for (int c = 0; c < 4; c++) acc[a][b][c] = 0.0f;

    const int lane = tid & 31, wid = tid >> 5;
    const int wm = wid & 3, wn = wid >> 2;   // 4(M) x 2(N) warps, warp tile 32x64

    for (int kt = 0; kt < 32; kt++) {
        asm volatile("cp.async.wait_group 1;");
        __syncthreads();
        if (kt + 2 < 32) load_stage(As, Bs, Ag, n_base, (kt + 2) % 3, kt + 2, tid);
        const int cur = kt % 3;
        uint32_t a_base = (uint32_t)__cvta_generic_to_shared(As + cur * STAGE_ELEMS);
        uint32_t b_base = (uint32_t)__cvta_generic_to_shared(Bs + cur * STAGE_ELEMS);
        #pragma unroll
        for (int ks = 0; ks < 2; ks++) {
            uint32_t af[2][4];
            #pragma unroll
            for (int mt = 0; mt < 2; mt++) {
                int row = wm * 32 + mt * 16 + (lane & 15);
                int col = ks * 16 + (lane >> 4) * 8;
                uint32_t ad = a_base + (uint32_t)(row * LDT + col) * 2;
                LDSM4(af[mt][0], af[mt][1], af[mt][2], af[mt][3], ad);
            }
            uint32_t bfr[8][2];
            #pragma unroll
            for (int np = 0; np < 4; np++) {
                int mi = lane >> 3;
                int nr = wn * 64 + np * 16 + (mi >> 1) * 8 + (lane & 7);
                int kc = ks * 16 + (mi & 1) * 8;
                uint32_t ad = b_base + (uint32_t)(nr * LDT + kc) * 2;
                uint32_t r0, r1, r2, r3;
                LDSM4(r0, r1, r2, r3, ad);
                bfr[np * 2][0] = r0; bfr[np * 2][1] = r1;
                bfr[np * 2 + 1][0] = r2; bfr[np * 2 + 1][1] = r3;
            }
            #pragma unroll
            for (int mt = 0; mt < 2; mt++)
                #pragma unroll
                for (int nt = 0; nt < 8; nt++)
                    mma16816(acc[mt][nt], af[mt], bfr[nt]);
        }
    }
    asm volatile("cp.async.wait_group 0;");
    __syncthreads();

    // ---- epilogue: stage fp32 into smem [128][EPIT] ----
    #pragma unroll
    for (int mt = 0; mt < 2; mt++) {
        #pragma unroll
        for (int nt = 0; nt < 8; nt++) {
            int r = wm * 32 + mt * 16 + (lane >> 2);
            int cb = wn * 64 + nt * 8 + 2 * (lane & 3);
            epi[r * EPIT + cb]           = acc[mt][nt][0];
            epi[r * EPIT + cb + 1]       = acc[mt][nt][1];
            epi[(r + 8) * EPIT + cb]     = acc[mt][nt][2];
            epi[(r + 8) * EPIT + cb + 1] = acc[mt][nt][3];
        }
    }
    __syncthreads();

    int nvalid = K_DIM - n_base; if (nvalid > 128) nvalid = 128;   // 128 or 56

    // bf16 score stores: warp w copies rows [16w,16w+16), lane = 16B chunk (8 cols)
    for (int r = wid * 16; r < wid * 16 + 16; r++) {
        int gi = bm * 128 + r;
        int c8 = lane;
        if (c8 * 8 < nvalid) {
            float4 f0 = *reinterpret_cast<float4*>(&epi[r * EPIT + c8 * 8]);
            float4 f1 = *reinterpret_cast<float4*>(&epi[r * EPIT + c8 * 8 + 4]);
            __nv_bfloat162 h0 = __floats2bfloat162_rn(f0.x, f0.y);
            __nv_bfloat162 h1 = __floats2bfloat162_rn(f0.z, f0.w);
            __nv_bfloat162 h2 = __floats2bfloat162_rn(f1.x, f1.y);
            __nv_bfloat162 h3 = __floats2bfloat162_rn(f1.z, f1.w);
            uint4 o;
            o.x = *reinterpret_cast<uint32_t*>(&h0);
            o.y = *reinterpret_cast<uint32_t*>(&h1);
            o.z = *reinterpret_cast<uint32_t*>(&h2);
            o.w = *reinterpret_cast<uint32_t*>(&h3);
            *(reinterpret_cast<uint4*>(g_scores[mat] + (size_t)gi * K_DIM + n_base) + c8) = o;
        }
    }

    // fused reductions. col sums use bf16-rounded values (consistent with passes);
    // E row sums use full fp32 (accuracy).
    if (tid < 128) {
        int c = tid;
        if (c < nvalid) {
            float s = 0.0f;
            #pragma unroll 4
            for (int r = 0; r < 128; r++) {
                float sr = __bfloat162float(__float2bfloat16(epi[r * EPIT + c]));
                s += __expf(sr * IEPS);
            }
            atomicAdd(&g_c[mat][0][n_base + c], s);
        }
    } else {
        int r = tid - 128;
        float s = 0.0f;
        for (int c = 0; c < nvalid; c++) s += __expf(epi[r * EPIT + c] * ITMP);
        atomicAdd(&g_E[mat][bm * 128 + r], s);
    }
}

// ---------------- row pass: p[it][i] = (1/K) * sum_j exp(s/eps) * rcp(c[it][j]) ----------------
__global__ void __launch_bounds__(256) row_pass(int iter) {
    const int mat = blockIdx.y;
    const int r0 = blockIdx.x * 32;
    const int wid = threadIdx.x >> 5, lane = threadIdx.x & 31;
    const float* cv = g_c[mat][iter];
    for (int rr = wid; rr < 32; rr += 8) {
        int i = r0 + rr;
        const uint4* srow = reinterpret_cast<const uint4*>(g_scores[mat] + (size_t)i * K_DIM);
        float acc = 0.0f;
        for (int j8 = lane; j8 < KC8; j8 += 32) {
            uint4 ch = srow[j8];
            float s[8]; unpack8(ch, s);
            float4 c0 = *reinterpret_cast<const float4*>(cv + j8 * 8);
            float4 c1 = *reinterpret_cast<const float4*>(cv + j8 * 8 + 4);
            acc += __expf(s[0] * IEPS) * frcp(c0.x) + __expf(s[1] * IEPS) * frcp(c0.y)
                 + __expf(s[2] * IEPS) * frcp(c0.z) + __expf(s[3] * IEPS) * frcp(c0.w)
                 + __expf(s[4] * IEPS) * frcp(c1.x) + __expf(s[5] * IEPS) * frcp(c1.y)
                 + __expf(s[6] * IEPS) * frcp(c1.z) + __expf(s[7] * IEPS) * frcp(c1.w);
        }
        acc = warp_red(acc);
        if (lane == 0) g_p[mat][iter][i] = acc * (1.0f / (float)K_DIM);
    }
}

// ---------------- col pass: c[it+1][j] = (1/B) * sum_i exp(s/eps) * rcp(p[it][i]) ----------------
__global__ void __launch_bounds__(256) col_pass(int iter) {
    const int mat = blockIdx.z;
    const int r0 = blockIdx.y * 128;
    __shared__ float su[128];
    if (threadIdx.x < 128)
        su[threadIdx.x] = frcp(g_p[mat][iter][r0 + threadIdx.x]);
    __syncthreads();
    const int j8 = blockIdx.x * blockDim.x + threadIdx.x;
    if (j8 >= KC8) return;
    const __nv_bfloat16* base = g_scores[mat];
    float a[8];
    #pragma unroll
    for (int k = 0; k < 8; k++) a[k] = 0.0f;
    for (int r = 0; r < 128; r++) {
        float u = su[r];
        uint4 ch = *(reinterpret_cast<const uint4*>(base + (size_t)(r0 + r) * K_DIM) + j8);
        float s[8]; unpack8(ch, s);
        #pragma unroll
        for (int k = 0; k < 8; k++) a[k] += __expf(s[k] * IEPS) * u;
    }
    float* c = g_c[mat][iter + 1];
    #pragma unroll
    for (int k = 0; k < 8; k++)
        atomicAdd(&c[j8 * 8 + k], a[k] * (1.0f / (float)B_DIM));
}

// ---------------- fused iter-2 row pass + cross terms ----------------
// p[m][2][i] = sum_j M_m v_m ; t[m][i] = sum_j M_m v_m * s_other
__global__ void __launch_bounds__(256) rowcross_kernel() {
    const int m = blockIdx.y, o = 1 - m;
    const int r0 = blockIdx.x * 32;
    const int wid = threadIdx.x >> 5, lane = threadIdx.x & 31;
    const float* cv = g_c[m][2];
    for (int rr = wid; rr < 32; rr += 8) {
        int i = r0 + rr;
        const uint4* sm = reinterpret_cast<const uint4*>(g_scores[m] + (size_t)i * K_DIM);
        const uint4* so = reinterpret_cast<const uint4*>(g_scores[o] + (size_t)i * K_DIM);
        float ap = 0.0f, at = 0.0f;
        for (int j8 = lane; j8 < KC8; j8 += 32) {
            uint4 chm = sm[j8], cho = so[j8];
            float s[8], x[8];
            unpack8(chm, s); unpack8(cho, x);
            float4 c0 = *reinterpret_cast<const float4*>(cv + j8 * 8);
            float4 c1 = *reinterpret_cast<const float4*>(cv + j8 * 8 + 4);
            float cc[8] = {c0.x, c0.y, c0.z, c0.w, c1.x, c1.y, c1.z, c1.w};
            #pragma unroll
            for (int k = 0; k < 8; k++) {
                float e = __expf(s[k] * IEPS) * frcp(cc[k]);
                ap += e;
                at += e * x[k];
            }
        }
        ap = warp_red(ap); at = warp_red(at);
        if (lane == 0) {
            g_p[m][2][i] = ap * (1.0f / (float)K_DIM);
            g_t[m][i]    = at * (1.0f / (float)K_DIM);
        }
    }
}

// ---------------- finalize ----------------
// A = sum_i t[m][i] / (B * p[m][2][i]) over both m; loss = -0.5*(A/(B*T) - sum(log E)/B^2)
__global__ void finalize_kernel(float* out) {
    float a = 0.0f, l = 0.0f;
    for (int i = threadIdx.x; i < B_DIM; i += blockDim.x) {
        a += g_t[0][i] / ((float)B_DIM * g_p[0][2][i])
           + g_t[1][i] / ((float)B_DIM * g_p[1][2][i]);
        l += __logf(g_E[0][i]) + __logf(g_E[1][i]);
    }
    a = warp_red(a); l = warp_red(l);
    __shared__ float sa[8], sl[8];
    int lane = threadIdx.x & 31, wid = threadIdx.x >> 5;
    if (lane == 0) { sa[wid] = a; sl[wid] = l; }
    __syncthreads();
    if (threadIdx.x == 0) {
        float ta = 0.f, tl = 0.f;
        for (int w = 0; w < 8; w++) { ta += sa[w]; tl += sl[w]; }
        float loss = -0.5f * (ta / ((float)B_DIM * TEMP)
                              - tl / ((float)B_DIM * (float)B_DIM));
        out[0] = loss;
    }
}

// ---------------- launch ----------------
extern "C" void kernel_launch(void* const* d_in, const int* in_sizes, int n_in,
                              void* d_out, int out_size) {
    const float* z1 = (const float*)d_in[0];
    const float* z2 = (const float*)d_in[1];
    const float* W  = (const float*)d_in[2];
    float* out = (float*)d_out;

    cudaFuncSetAttribute(gemm_kernel, cudaFuncAttributeMaxDynamicSharedMemorySize, DYN_SMEM);

    cvt_kernel<<<2048, 256>>>(z1, z2, W);

    dim3 ggrid(24, 32, 2);
    gemm_kernel<<<ggrid, 256, DYN_SMEM>>>();

    // iter 0 col sums came from GEMM epilogue
    row_pass<<<dim3(128, 2), 256>>>(0);
    col_pass<<<dim3(2, 32, 2), 256>>>(0);
    row_pass<<<dim3(128, 2), 256>>>(1);
    col_pass<<<dim3(2, 32, 2), 256>>>(1);
    rowcross_kernel<<<dim3(128, 2), 256>>>();
    finalize_kernel<<<1, 256>>>(out);
}

// round 5
// speedup vs baseline: 1.1936x; 1.0657x over previous
#include <cuda_runtime.h>
#include <cuda_bf16.h>
#include <cuda_fp16.h>
#include <cstdint>

#define B_DIM 4096
#define D_DIM 1024
#define K_DIM 3000
#define KC8   375          // K_DIM / 8 : 16B chunks per 16-bit row
#define KP    3008
#define IEPS  20.0f        // 1/epsilon
#define ITMP  10.0f        // 1/temperature
#define TEMP  0.1f
#define EPIT  132          // epilogue smem pitch (floats), 16B-aligned rows

// ---------------- scratch ----------------
__device__ __align__(256) __nv_bfloat16  g_scores[2][(size_t)B_DIM * K_DIM]; // 49.2 MB (s)
__device__ __align__(256) __half         g_M[2][(size_t)B_DIM * K_DIM];      // 49.2 MB (exp(s/eps))
__device__ __align__(256) __nv_bfloat16  g_zb[2][(size_t)B_DIM * D_DIM];     // 16.8 MB
__device__ __align__(256) __nv_bfloat16  g_Wb[(size_t)K_DIM * D_DIM];        //  6.1 MB
__device__ __align__(256) float          g_c [2][3][KP];     // col sums per iter
__device__ __align__(256) float          g_p [2][3][B_DIM];  // row sums per iter
__device__ __align__(256) float          g_E [2][B_DIM];     // exp(s/T) row sums
__device__ __align__(256) float          g_t [2][B_DIM];     // cross-term row vectors

// ---------------- helpers ----------------
__device__ __forceinline__ float warp_red(float v) {
    #pragma unroll
    for (int o = 16; o; o >>= 1) v += __shfl_xor_sync(0xffffffffu, v, o);
    return v;
}
__device__ __forceinline__ float frcp(float x) {
    float r; asm("rcp.approx.f32 %0, %1;" : "=f"(r) : "f"(x)); return r;
}
__device__ __forceinline__ void unpack8h(uint4 ch, float* f) {
    __half2* h = reinterpret_cast<__half2*>(&ch);
    #pragma unroll
    for (int k = 0; k < 4; k++) {
        float2 t = __half22float2(h[k]);
        f[2 * k] = t.x; f[2 * k + 1] = t.y;
    }
}
__device__ __forceinline__ void unpack8b(uint4 ch, float* f) {
    __nv_bfloat162* h = reinterpret_cast<__nv_bfloat162*>(&ch);
    #pragma unroll
    for (int k = 0; k < 4; k++) {
        float2 t = __bfloat1622float2(h[k]);
        f[2 * k] = t.x; f[2 * k + 1] = t.y;
    }
}

// ---------------- cvt + zero (fused) ----------------
__global__ void cvt_kernel(const float* __restrict__ z1,
                           const float* __restrict__ z2,
                           const float* __restrict__ W) {
    const int n1 = B_DIM * D_DIM;
    const int nw = K_DIM * D_DIM;
    int idx0 = blockIdx.x * blockDim.x + threadIdx.x;
    if (idx0 < 2 * 3 * KP)  ((float*)g_c)[idx0] = 0.0f;
    if (idx0 < 2 * B_DIM)   ((float*)g_E)[idx0] = 0.0f;
    int stride = gridDim.x * blockDim.x;
    for (int i = idx0; i < n1; i += stride) {
        g_zb[0][i] = __float2bfloat16(z1[i]);
        g_zb[1][i] = __float2bfloat16(z2[i]);
        if (i < nw) g_Wb[i] = __float2bfloat16(W[i]);
    }
}

// ---------------- GEMM: mma.sync bf16, 128x128x32, 3-stage cp.async ----------------
#define STAGE_ELEMS 5120
#define LDT 40
#define DYN_SMEM 69632

__device__ __forceinline__ void cp16(void* sdst, const void* gsrc) {
    uint32_t s = (uint32_t)__cvta_generic_to_shared(sdst);
    asm volatile("cp.async.cg.shared.global [%0], [%1], 16;" :: "r"(s), "l"(gsrc));
}

#define LDSM4(R0,R1,R2,R3,ADDR) \
    asm volatile("ldmatrix.sync.aligned.m8n8.x4.shared.b16 {%0,%1,%2,%3}, [%4];" \
                 : "=r"(R0), "=r"(R1), "=r"(R2), "=r"(R3) : "r"(ADDR))

__device__ __forceinline__ void mma16816(float* c, const uint32_t* a, const uint32_t* b) {
    asm volatile(
        "mma.sync.aligned.m16n8k16.row.col.f32.bf16.bf16.f32 "
        "{%0,%1,%2,%3}, {%4,%5,%6,%7}, {%8,%9}, {%0,%1,%2,%3};"
        : "+f"(c[0]), "+f"(c[1]), "+f"(c[2]), "+f"(c[3])
        : "r"(a[0]), "r"(a[1]), "r"(a[2]), "r"(a[3]), "r"(b[0]), "r"(b[1]));
}

__device__ __forceinline__ void load_stage(__nv_bfloat16* As, __nv_bfloat16* Bs,
                                           const __nv_bfloat16* Ag, int n_base,
                                           int s, int kt, int tid) {
    #pragma unroll
    for (int h = 0; h < 2; h++) {
        int c = tid + h * 256;
        int r = c >> 2, c16 = c & 3;
        cp16(As + s * STAGE_ELEMS + r * LDT + c16 * 8,
             Ag + (size_t)r * D_DIM + kt * 32 + c16 * 8);
    }
    #pragma unroll
    for (int h = 0; h < 2; h++) {
        int c = tid + h * 256;
        int r = c >> 2, c16 = c & 3;
        int gn = n_base + r; if (gn >= K_DIM) gn = K_DIM - 1;   // clamp tail
        cp16(Bs + s * STAGE_ELEMS + r * LDT + c16 * 8,
             g_Wb + (size_t)gn * D_DIM + kt * 32 + c16 * 8);
    }
    asm volatile("cp.async.commit_group;");
}

__global__ void __launch_bounds__(256, 2) gemm_kernel() {
    extern __shared__ char smem_raw[];
    __nv_bfloat16* As = reinterpret_cast<__nv_bfloat16*>(smem_raw);
    __nv_bfloat16* Bs = As + 3 * STAGE_ELEMS;
    float* epi = reinterpret_cast<float*>(smem_raw);

    const int tid = threadIdx.x;
    const int bn = blockIdx.x, bm = blockIdx.y, mat = blockIdx.z;
    const __nv_bfloat16* Ag = g_zb[mat] + (size_t)bm * 128 * D_DIM;
    const int n_base = bn * 128;

    load_stage(As, Bs, Ag, n_base, 0, 0, tid);
    load_stage(As, Bs, Ag, n_base, 1, 1, tid);

    float acc[2][8][4];
    #pragma unroll
    for (int a = 0; a < 2; a++)
        #pragma unroll
        for (int b = 0; b < 8; b++)
            #pragma unroll
            for (int c = 0; c < 4; c++) acc[a][b][c] = 0.0f;

    const int lane = tid & 31, wid = tid >> 5;
    const int wm = wid & 3, wn = wid >> 2;

    for (int kt = 0; kt < 32; kt++) {
        asm volatile("cp.async.wait_group 1;");
        __syncthreads();
        if (kt + 2 < 32) load_stage(As, Bs, Ag, n_base, (kt + 2) % 3, kt + 2, tid);
        const int cur = kt % 3;
        uint32_t a_base = (uint32_t)__cvta_generic_to_shared(As + cur * STAGE_ELEMS);
        uint32_t b_base = (uint32_t)__cvta_generic_to_shared(Bs + cur * STAGE_ELEMS);
        #pragma unroll
        for (int ks = 0; ks < 2; ks++) {
            uint32_t af[2][4];
            #pragma unroll
            for (int mt = 0; mt < 2; mt++) {
                int row = wm * 32 + mt * 16 + (lane & 15);
                int col = ks * 16 + (lane >> 4) * 8;
                uint32_t ad = a_base + (uint32_t)(row * LDT + col) * 2;
                LDSM4(af[mt][0], af[mt][1], af[mt][2], af[mt][3], ad);
            }
            uint32_t bfr[8][2];
            #pragma unroll
            for (int np = 0; np < 4; np++) {
                int mi = lane >> 3;
                int nr = wn * 64 + np * 16 + (mi >> 1) * 8 + (lane & 7);
                int kc = ks * 16 + (mi & 1) * 8;
                uint32_t ad = b_base + (uint32_t)(nr * LDT + kc) * 2;
                uint32_t r0, r1, r2, r3;
                LDSM4(r0, r1, r2, r3, ad);
                bfr[np * 2][0] = r0; bfr[np * 2][1] = r1;
                bfr[np * 2 + 1][0] = r2; bfr[np * 2 + 1][1] = r3;
            }
            #pragma unroll
            for (int mt = 0; mt < 2; mt++)
                #pragma unroll
                for (int nt = 0; nt < 8; nt++)
                    mma16816(acc[mt][nt], af[mt], bfr[nt]);
        }
    }
    asm volatile("cp.async.wait_group 0;");
    __syncthreads();

    // ---- epilogue: stage fp32 into smem [128][EPIT] ----
    #pragma unroll
    for (int mt = 0; mt < 2; mt++) {
        #pragma unroll
        for (int nt = 0; nt < 8; nt++) {
            int r = wm * 32 + mt * 16 + (lane >> 2);
            int cb = wn * 64 + nt * 8 + 2 * (lane & 3);
            epi[r * EPIT + cb]           = acc[mt][nt][0];
            epi[r * EPIT + cb + 1]       = acc[mt][nt][1];
            epi[(r + 8) * EPIT + cb]     = acc[mt][nt][2];
            epi[(r + 8) * EPIT + cb + 1] = acc[mt][nt][3];
        }
    }
    __syncthreads();

    int nvalid = K_DIM - n_base; if (nvalid > 128) nvalid = 128;   // 128 or 56

    // store s (bf16) + M=exp(s/eps) (fp16) + column sums of M, warp w -> rows [16w,16w+16)
    {
        int c8 = lane;
        bool act = (c8 * 8 < nvalid);
        float colacc[8];
        #pragma unroll
        for (int k = 0; k < 8; k++) colacc[k] = 0.0f;
        for (int r = wid * 16; r < wid * 16 + 16; r++) {
            int gi = bm * 128 + r;
            if (act) {
                float f[8];
                *reinterpret_cast<float4*>(f)     = *reinterpret_cast<float4*>(&epi[r * EPIT + c8 * 8]);
                *reinterpret_cast<float4*>(f + 4) = *reinterpret_cast<float4*>(&epi[r * EPIT + c8 * 8 + 4]);
                // s -> bf16
                uint4 os;
                __nv_bfloat162 b0 = __floats2bfloat162_rn(f[0], f[1]);
                __nv_bfloat162 b1 = __floats2bfloat162_rn(f[2], f[3]);
                __nv_bfloat162 b2 = __floats2bfloat162_rn(f[4], f[5]);
                __nv_bfloat162 b3 = __floats2bfloat162_rn(f[6], f[7]);
                os.x = *reinterpret_cast<uint32_t*>(&b0);
                os.y = *reinterpret_cast<uint32_t*>(&b1);
                os.z = *reinterpret_cast<uint32_t*>(&b2);
                os.w = *reinterpret_cast<uint32_t*>(&b3);
                *(reinterpret_cast<uint4*>(g_scores[mat] + (size_t)gi * K_DIM + n_base) + c8) = os;
                // M -> fp16, accumulate column sums
                float m[8];
                #pragma unroll
                for (int k = 0; k < 8; k++) { m[k] = __expf(f[k] * IEPS); colacc[k] += m[k]; }
                uint4 om;
                __half2 h0 = __floats2half2_rn(m[0], m[1]);
                __half2 h1 = __floats2half2_rn(m[2], m[3]);
                __half2 h2 = __floats2half2_rn(m[4], m[5]);
                __half2 h3 = __floats2half2_rn(m[6], m[7]);
                om.x = *reinterpret_cast<uint32_t*>(&h0);
                om.y = *reinterpret_cast<uint32_t*>(&h1);
                om.z = *reinterpret_cast<uint32_t*>(&h2);
                om.w = *reinterpret_cast<uint32_t*>(&h3);
                *(reinterpret_cast<uint4*>(g_M[mat] + (size_t)gi * K_DIM + n_base) + c8) = om;
            }
        }
        if (act) {
            #pragma unroll
            for (int k = 0; k < 8; k++)
                atomicAdd(&g_c[mat][0][n_base + c8 * 8 + k], colacc[k]);
        }
    }

    // E row sums: exp(s/T), warp per 16 rows, lanes stride columns
    for (int r = wid * 16; r < wid * 16 + 16; r++) {
        float s = 0.0f;
        for (int c = lane; c < nvalid; c += 32) s += __expf(epi[r * EPIT + c] * ITMP);
        s = warp_red(s);
        if (lane == 0) atomicAdd(&g_E[mat][bm * 128 + r], s);
    }
}

// ---------------- row pass: p[it][i] = (1/K) * sum_j M_ij * rcp(c[it][j]) ----------------
// grid (128, 2), block 256; 32 rows per block, 4 rows per warp
__global__ void __launch_bounds__(256) row_pass(int iter) {
    const int mat = blockIdx.y;
    const int r0 = blockIdx.x * 32;
    __shared__ float sv[KP];
    {
        const float4* c4 = reinterpret_cast<const float4*>(g_c[mat][iter]);
        for (int j4 = threadIdx.x; j4 < KP / 4; j4 += 256) {
            float4 c = c4[j4];
            float4 v = make_float4(frcp(c.x), frcp(c.y), frcp(c.z), frcp(c.w));
            *reinterpret_cast<float4*>(&sv[j4 * 4]) = v;
        }
    }
    __syncthreads();
    const int wid = threadIdx.x >> 5, lane = threadIdx.x & 31;
    for (int rr = wid; rr < 32; rr += 8) {
        int i = r0 + rr;
        const uint4* mrow = reinterpret_cast<const uint4*>(g_M[mat] + (size_t)i * K_DIM);
        float acc = 0.0f;
        for (int j8 = lane; j8 < KC8; j8 += 32) {
            uint4 ch = mrow[j8];
            float m[8]; unpack8h(ch, m);
            float4 v0 = *reinterpret_cast<const float4*>(&sv[j8 * 8]);
            float4 v1 = *reinterpret_cast<const float4*>(&sv[j8 * 8 + 4]);
            acc += m[0] * v0.x + m[1] * v0.y + m[2] * v0.z + m[3] * v0.w
                 + m[4] * v1.x + m[5] * v1.y + m[6] * v1.z + m[7] * v1.w;
        }
        acc = warp_red(acc);
        if (lane == 0) g_p[mat][iter][i] = acc * (1.0f / (float)K_DIM);
    }
}

// ---------------- col pass: c[it+1][j] = (1/B) * sum_i M_ij * rcp(p[it][i]) ----------------
// grid (2, 64, 2), block 256; 64-row groups
__global__ void __launch_bounds__(256) col_pass(int iter) {
    const int mat = blockIdx.z;
    const int r0 = blockIdx.y * 64;
    __shared__ float su[64];
    if (threadIdx.x < 64)
        su[threadIdx.x] = frcp(g_p[mat][iter][r0 + threadIdx.x]);
    __syncthreads();
    const int j8 = blockIdx.x * blockDim.x + threadIdx.x;
    if (j8 >= KC8) return;
    const __half* base = g_M[mat];
    float a[8];
    #pragma unroll
    for (int k = 0; k < 8; k++) a[k] = 0.0f;
    for (int r = 0; r < 64; r++) {
        float u = su[r];
        uint4 ch = *(reinterpret_cast<const uint4*>(base + (size_t)(r0 + r) * K_DIM) + j8);
        float m[8]; unpack8h(ch, m);
        #pragma unroll
        for (int k = 0; k < 8; k++) a[k] += m[k] * u;
    }
    float* c = g_c[mat][iter + 1];
    #pragma unroll
    for (int k = 0; k < 8; k++)
        atomicAdd(&c[j8 * 8 + k], a[k] * (1.0f / (float)B_DIM));
}

// ---------------- fused iter-2 row pass + cross terms ----------------
// p[m][2][i] = (1/K) sum_j M/c2 ;  t[m][i] = (1/K) sum_j (M/c2) * s_other
__global__ void __launch_bounds__(256) rowcross_kernel() {
    const int m = blockIdx.y, o = 1 - m;
    const int r0 = blockIdx.x * 32;
    __shared__ float sv[KP];
    {
        const float4* c4 = reinterpret_cast<const float4*>(g_c[m][2]);
        for (int j4 = threadIdx.x; j4 < KP / 4; j4 += 256) {
            float4 c = c4[j4];
            float4 v = make_float4(frcp(c.x), frcp(c.y), frcp(c.z), frcp(c.w));
            *reinterpret_cast<float4*>(&sv[j4 * 4]) = v;
        }
    }
    __syncthreads();
    const int wid = threadIdx.x >> 5, lane = threadIdx.x & 31;
    for (int rr = wid; rr < 32; rr += 8) {
        int i = r0 + rr;
        const uint4* mrow = reinterpret_cast<const uint4*>(g_M[m] + (size_t)i * K_DIM);
        const uint4* srow = reinterpret_cast<const uint4*>(g_scores[o] + (size_t)i * K_DIM);
        float ap = 0.0f, at = 0.0f;
        for (int j8 = lane; j8 < KC8; j8 += 32) {
            uint4 chm = mrow[j8], cho = srow[j8];
            float mm[8], x[8];
            unpack8h(chm, mm); unpack8b(cho, x);
            float4 v0 = *reinterpret_cast<const float4*>(&sv[j8 * 8]);
            float4 v1 = *reinterpret_cast<const float4*>(&sv[j8 * 8 + 4]);
            float vv[8] = {v0.x, v0.y, v0.z, v0.w, v1.x, v1.y, v1.z, v1.w};
            #pragma unroll
            for (int k = 0; k < 8; k++) {
                float e = mm[k] * vv[k];
                ap += e;
                at += e * x[k];
            }
        }
        ap = warp_red(ap); at = warp_red(at);
        if (lane == 0) {
            g_p[m][2][i] = ap * (1.0f / (float)K_DIM);
            g_t[m][i]    = at * (1.0f / (float)K_DIM);
        }
    }
}

// ---------------- finalize ----------------
__global__ void finalize_kernel(float* out) {
    float a = 0.0f, l = 0.0f;
    for (int i = threadIdx.x; i < B_DIM; i += blockDim.x) {
        a += g_t[0][i] / ((float)B_DIM * g_p[0][2][i])
           + g_t[1][i] / ((float)B_DIM * g_p[1][2][i]);
        l += __logf(g_E[0][i]) + __logf(g_E[1][i]);
    }
    a = warp_red(a); l = warp_red(l);
    __shared__ float sa[8], sl[8];
    int lane = threadIdx.x & 31, wid = threadIdx.x >> 5;
    if (lane == 0) { sa[wid] = a; sl[wid] = l; }
    __syncthreads();
    if (threadIdx.x == 0) {
        float ta = 0.f, tl = 0.f;
        for (int w = 0; w < 8; w++) { ta += sa[w]; tl += sl[w]; }
        float loss = -0.5f * (ta / ((float)B_DIM * TEMP)
                              - tl / ((float)B_DIM * (float)B_DIM));
        out[0] = loss;
    }
}

// ---------------- launch ----------------
extern "C" void kernel_launch(void* const* d_in, const int* in_sizes, int n_in,
                              void* d_out, int out_size) {
    const float* z1 = (const float*)d_in[0];
    const float* z2 = (const float*)d_in[1];
    const float* W  = (const float*)d_in[2];
    float* out = (float*)d_out;

    cudaFuncSetAttribute(gemm_kernel, cudaFuncAttributeMaxDynamicSharedMemorySize, DYN_SMEM);

    cvt_kernel<<<2048, 256>>>(z1, z2, W);

    dim3 ggrid(24, 32, 2);
    gemm_kernel<<<ggrid, 256, DYN_SMEM>>>();

    // iter 0 col sums came from GEMM epilogue
    row_pass<<<dim3(128, 2), 256>>>(0);
    col_pass<<<dim3(2, 64, 2), 256>>>(0);
    row_pass<<<dim3(128, 2), 256>>>(1);
    col_pass<<<dim3(2, 64, 2), 256>>>(1);
    rowcross_kernel<<<dim3(128, 2), 256>>>();
    finalize_kernel<<<1, 256>>>(out);
}